// round 1
// baseline (speedup 1.0000x reference)
#include <cuda_runtime.h>

// Problem constants (fixed by the reference)
#define BATCH   4096
#define NDIM    128
#define N_ITERS 4000
#define C_RAMP  0.5f

// One warp per batch item. Lane l owns elements 4l..4l+3 of z/p/d and of
// nu/y (dual, length 127; global index 127 is held as an always-zero slot
// in lane 31's j=3 position).
//
// Per iteration:
//   z[i]  = -(p[i] + y[i] - y[i-1]) / d[i]          (y[-1]=y[127]=0)
//   g[i]  = z[i] - z[i+1]                           (i < 127)
//   nu'   = soft(y + alpha*g, alpha*C_RAMP)
//   t'    = (1 + sqrt(1+4t^2))/2 ;  y = nu' + ((t-1)/t')*(nu' - nu)
// Only cross-lane data: y[4l-1] (shfl_up of y3) and z[4l+4] (shfl_down of z0).

__global__ __launch_bounds__(256, 8)
void fista_warp_kernel(const float* __restrict__ z0,
                       const float* __restrict__ mu,
                       const float* __restrict__ dg,
                       const float* __restrict__ d2g,
                       float* __restrict__ out)
{
    const unsigned FULL = 0xffffffffu;
    int gwarp = (blockIdx.x * blockDim.x + threadIdx.x) >> 5;
    int lane  = threadIdx.x & 31;
    if (gwarp >= BATCH) return;

    // Coalesced float4 loads: lane l reads elements 4l..4l+3 of item gwarp.
    size_t vbase = (size_t)gwarp * (NDIM / 4) + lane;
    float4 z4 = ((const float4*)z0)[vbase];
    float4 m4 = ((const float4*)mu)[vbase];
    float4 g4 = ((const float4*)dg)[vbase];
    float4 h4 = ((const float4*)d2g)[vbase];

    // d = d2g + 1 ; p = dg - d2g*z0 - mu ; nid = -1/d
    float d0 = h4.x + 1.0f, d1 = h4.y + 1.0f, d2 = h4.z + 1.0f, d3 = h4.w + 1.0f;
    float p0 = fmaf(-h4.x, z4.x, g4.x) - m4.x;
    float p1 = fmaf(-h4.y, z4.y, g4.y) - m4.y;
    float p2 = fmaf(-h4.z, z4.z, g4.z) - m4.z;
    float p3 = fmaf(-h4.w, z4.w, g4.w) - m4.w;
    float nid0 = -1.0f / d0, nid1 = -1.0f / d1, nid2 = -1.0f / d2, nid3 = -1.0f / d3;

    // alpha = min(d)/4 over the item (warp reduction)
    float dmin = fminf(fminf(d0, d1), fminf(d2, d3));
    #pragma unroll
    for (int o = 16; o; o >>= 1)
        dmin = fminf(dmin, __shfl_xor_sync(FULL, dmin, o));
    float alpha = dmin * 0.25f;
    float thr   = alpha * C_RAMP;

    // FISTA state in registers
    float nu0 = 0.f, nu1 = 0.f, nu2 = 0.f, nu3 = 0.f;
    float y0 = 0.f, y1 = 0.f, y2 = 0.f, y3 = 0.f;
    float t = 1.0f;

    #pragma unroll 2
    for (int it = 0; it < N_ITERS; ++it) {
        // left neighbor of this lane's first y element
        float ylm = __shfl_up_sync(FULL, y3, 1);
        if (lane == 0) ylm = 0.0f;

        // z = -(p + DT(y))/d   (lane31: y3 is the always-zero slot ->
        //  zz3 = -(p3 - y2)/d3 which is exactly DT[127] = -y[126])
        float zz0 = (p0 + (y0 - ylm)) * nid0;
        float zz1 = (p1 + (y1 - y0 )) * nid1;
        float zz2 = (p2 + (y2 - y1 )) * nid2;
        float zz3 = (p3 + (y3 - y2 )) * nid3;

        // right neighbor z for the last g of this lane
        float zn = __shfl_down_sync(FULL, zz0, 1);   // z[4l+4]

        // x = y + alpha * D(z)
        float x0 = fmaf(alpha, zz0 - zz1, y0);
        float x1 = fmaf(alpha, zz1 - zz2, y1);
        float x2 = fmaf(alpha, zz2 - zz3, y2);
        float x3 = fmaf(alpha, zz3 - zn , y3);

        // soft threshold
        float n0 = copysignf(fmaxf(fabsf(x0) - thr, 0.0f), x0);
        float n1 = copysignf(fmaxf(fabsf(x1) - thr, 0.0f), x1);
        float n2 = copysignf(fmaxf(fabsf(x2) - thr, 0.0f), x2);
        float n3 = copysignf(fmaxf(fabsf(x3) - thr, 0.0f), x3);
        if (lane == 31) n3 = 0.0f;   // dual index 127 does not exist

        // momentum
        float tn   = 0.5f * (1.0f + sqrtf(fmaf(4.0f * t, t, 1.0f)));
        float beta = (t - 1.0f) / tn;
        y0 = fmaf(beta, n0 - nu0, n0); nu0 = n0;
        y1 = fmaf(beta, n1 - nu1, n1); nu1 = n1;
        y2 = fmaf(beta, n2 - nu2, n2); nu2 = n2;
        y3 = fmaf(beta, n3 - nu3, n3); nu3 = n3;
        t = tn;
    }

    // z* = z_of(nu) with the FINAL nu (not y)
    float num = __shfl_up_sync(FULL, nu3, 1);
    if (lane == 0) num = 0.0f;
    float4 o4;
    o4.x = (p0 + (nu0 - num)) * nid0;
    o4.y = (p1 + (nu1 - nu0)) * nid1;
    o4.z = (p2 + (nu2 - nu1)) * nid2;
    o4.w = (p3 + (nu3 - nu2)) * nid3;
    ((float4*)out)[vbase] = o4;
}

extern "C" void kernel_launch(void* const* d_in, const int* in_sizes, int n_in,
                              void* d_out, int out_size)
{
    const float* z0  = (const float*)d_in[0];
    const float* mu  = (const float*)d_in[1];
    const float* dg  = (const float*)d_in[2];
    const float* d2g = (const float*)d_in[3];
    float* out = (float*)d_out;

    // 4096 warps, 8 warps (256 threads) per block -> 512 blocks
    dim3 block(256);
    dim3 grid((BATCH * 32) / 256);
    fista_warp_kernel<<<grid, block>>>(z0, mu, dg, d2g, out);
}

// round 2
// speedup vs baseline: 11.7772x; 11.7772x over previous
#include <cuda_runtime.h>

// Batched FISTA on the dual of a ramp-constrained QP.
// One warp per batch item; 4 elements per lane, all state in registers.
#define BATCH   4096
#define NDIM    128
#define C_RAMP  0.5f
#define N_BLKS  80      // 80 * 50 = 4000 iterations max (matches reference)
#define BLK_IT  50
#define TOL     1e-6f   // prox-gradient residual (inf-norm) for early exit

__global__ __launch_bounds__(128)
void fista_warp_kernel(const float* __restrict__ z0,
                       const float* __restrict__ mu,
                       const float* __restrict__ dg,
                       const float* __restrict__ d2g,
                       float* __restrict__ out)
{
    const unsigned FULL = 0xffffffffu;
    int gwarp = (blockIdx.x * blockDim.x + threadIdx.x) >> 5;
    int lane  = threadIdx.x & 31;

    size_t vbase = (size_t)gwarp * (NDIM / 4) + lane;
    float4 z4 = ((const float4*)z0)[vbase];
    float4 m4 = ((const float4*)mu)[vbase];
    float4 g4 = ((const float4*)dg)[vbase];
    float4 h4 = ((const float4*)d2g)[vbase];

    // d = d2g + 1 ; p = dg - d2g*z0 - mu ; nid = -1/d ; pn = p*nid
    float d0 = h4.x + 1.0f, d1 = h4.y + 1.0f, d2 = h4.z + 1.0f, d3 = h4.w + 1.0f;
    float p0 = fmaf(-h4.x, z4.x, g4.x) - m4.x;
    float p1 = fmaf(-h4.y, z4.y, g4.y) - m4.y;
    float p2 = fmaf(-h4.z, z4.z, g4.z) - m4.z;
    float p3 = fmaf(-h4.w, z4.w, g4.w) - m4.w;
    float nid0 = -1.0f / d0, nid1 = -1.0f / d1, nid2 = -1.0f / d2, nid3 = -1.0f / d3;
    float pn0 = p0 * nid0, pn1 = p1 * nid1, pn2 = p2 * nid2, pn3 = p3 * nid3;

    // alpha = min(d)/4 per item
    float dmin = fminf(fminf(d0, d1), fminf(d2, d3));
    #pragma unroll
    for (int o = 16; o; o >>= 1)
        dmin = fminf(dmin, __shfl_xor_sync(FULL, dmin, o));
    float alpha = dmin * 0.25f;
    float thr   = alpha * C_RAMP;

    float nu0 = 0.f, nu1 = 0.f, nu2 = 0.f, nu3 = 0.f;
    float y0 = 0.f, y1 = 0.f, y2 = 0.f, y3 = 0.f;
    float t = 1.0f;

    const bool lane0  = (lane == 0);
    const bool lane31 = (lane == 31);

    // One FISTA iteration. TRACK=true additionally returns the prox-gradient
    // residual max_i |n_i - y_i| (a snapshot optimality measure).
    #define FISTA_STEP(TRACK, RES)                                           \
    {                                                                        \
        float ylm = __shfl_up_sync(FULL, y3, 1);                             \
        if (lane0) ylm = 0.0f;                                               \
        float zz0 = fmaf(y0 - ylm, nid0, pn0);                               \
        float zz1 = fmaf(y1 - y0 , nid1, pn1);                               \
        float zz2 = fmaf(y2 - y1 , nid2, pn2);                               \
        float zz3 = fmaf(y3 - y2 , nid3, pn3);                               \
        float zn  = __shfl_down_sync(FULL, zz0, 1);                          \
        float x0 = fmaf(alpha, zz0 - zz1, y0);                               \
        float x1 = fmaf(alpha, zz1 - zz2, y1);                               \
        float x2 = fmaf(alpha, zz2 - zz3, y2);                               \
        float x3 = fmaf(alpha, zz3 - zn , y3);                               \
        /* soft threshold via clamp: n = x - clamp(x, -thr, thr) */          \
        float n0 = x0 - fminf(fmaxf(x0, -thr), thr);                         \
        float n1 = x1 - fminf(fmaxf(x1, -thr), thr);                         \
        float n2 = x2 - fminf(fmaxf(x2, -thr), thr);                         \
        float n3 = x3 - fminf(fmaxf(x3, -thr), thr);                         \
        if (lane31) n3 = 0.0f;                                               \
        if (TRACK) {                                                         \
            float r01 = fmaxf(fabsf(n0 - y0), fabsf(n1 - y1));               \
            float r23 = fmaxf(fabsf(n2 - y2), fabsf(n3 - y3));               \
            RES = fmaxf(r01, r23);                                           \
        }                                                                    \
        /* momentum: tn = 0.5 + sqrt(t^2 + 0.25); beta = (t-1)/tn (approx) */\
        float tt = fmaf(t, t, 0.25f);                                        \
        float s; asm("sqrt.approx.f32 %0, %1;" : "=f"(s) : "f"(tt));         \
        float tn = s + 0.5f;                                                 \
        float rn; asm("rcp.approx.f32 %0, %1;" : "=f"(rn) : "f"(tn));        \
        float beta = (t - 1.0f) * rn;                                        \
        t = tn;                                                              \
        y0 = fmaf(beta, n0 - nu0, n0); nu0 = n0;                             \
        y1 = fmaf(beta, n1 - nu1, n1); nu1 = n1;                             \
        y2 = fmaf(beta, n2 - nu2, n2); nu2 = n2;                             \
        y3 = fmaf(beta, n3 - nu3, n3); nu3 = n3;                             \
    }

    for (int blk = 0; blk < N_BLKS; ++blk) {
        float dummy;
        #pragma unroll 7
        for (int j = 0; j < BLK_IT - 1; ++j)
            FISTA_STEP(false, dummy)

        float res;
        FISTA_STEP(true, res)

        // warp-max of residual, uniform early exit
        #pragma unroll
        for (int o = 16; o; o >>= 1)
            res = fmaxf(res, __shfl_xor_sync(FULL, res, o));
        if (res < TOL) break;
    }

    // z* from the FINAL nu
    float num = __shfl_up_sync(FULL, nu3, 1);
    if (lane0) num = 0.0f;
    float4 o4;
    o4.x = fmaf(nu0 - num, nid0, pn0);
    o4.y = fmaf(nu1 - nu0, nid1, pn1);
    o4.z = fmaf(nu2 - nu1, nid2, pn2);
    o4.w = fmaf(nu3 - nu2, nid3, pn3);
    ((float4*)out)[vbase] = o4;
}

extern "C" void kernel_launch(void* const* d_in, const int* in_sizes, int n_in,
                              void* d_out, int out_size)
{
    const float* z0  = (const float*)d_in[0];
    const float* mu  = (const float*)d_in[1];
    const float* dg  = (const float*)d_in[2];
    const float* d2g = (const float*)d_in[3];
    float* out = (float*)d_out;

    dim3 block(128);
    dim3 grid((BATCH * 32) / 128);   // 1024 blocks, 4 warps each
    fista_warp_kernel<<<grid, block>>>(z0, mu, dg, d2g, out);
}

// round 3
// speedup vs baseline: 36.0728x; 3.0629x over previous
#include <cuda_runtime.h>

// Batched FISTA (+ gradient restart) on the dual of a ramp-constrained QP.
// One warp per batch item; 4 elements per lane, all state in registers.
#define BATCH   4096
#define NDIM    128
#define C_RAMP  0.5f
#define N_BLKS  250     // 250 * 16 = 4000 iterations max (matches reference)
#define BLK_IT  16
#define TOL     3e-5f   // prox-gradient residual (inf-norm) for early exit

__global__ __launch_bounds__(128)
void fista_warp_kernel(const float* __restrict__ z0,
                       const float* __restrict__ mu,
                       const float* __restrict__ dg,
                       const float* __restrict__ d2g,
                       float* __restrict__ out)
{
    const unsigned FULL = 0xffffffffu;
    int gwarp = (blockIdx.x * blockDim.x + threadIdx.x) >> 5;
    int lane  = threadIdx.x & 31;

    size_t vbase = (size_t)gwarp * (NDIM / 4) + lane;
    float4 z4 = ((const float4*)z0)[vbase];
    float4 m4 = ((const float4*)mu)[vbase];
    float4 g4 = ((const float4*)dg)[vbase];
    float4 h4 = ((const float4*)d2g)[vbase];

    // d = d2g + 1 ; p = dg - d2g*z0 - mu ; nid = -1/d ; pn = p*nid
    float d0 = h4.x + 1.0f, d1 = h4.y + 1.0f, d2 = h4.z + 1.0f, d3 = h4.w + 1.0f;
    float p0 = fmaf(-h4.x, z4.x, g4.x) - m4.x;
    float p1 = fmaf(-h4.y, z4.y, g4.y) - m4.y;
    float p2 = fmaf(-h4.z, z4.z, g4.z) - m4.z;
    float p3 = fmaf(-h4.w, z4.w, g4.w) - m4.w;
    float nid0 = -1.0f / d0, nid1 = -1.0f / d1, nid2 = -1.0f / d2, nid3 = -1.0f / d3;
    float pn0 = p0 * nid0, pn1 = p1 * nid1, pn2 = p2 * nid2, pn3 = p3 * nid3;

    // alpha = min(d)/4 per item
    float dmin = fminf(fminf(d0, d1), fminf(d2, d3));
    #pragma unroll
    for (int o = 16; o; o >>= 1)
        dmin = fminf(dmin, __shfl_xor_sync(FULL, dmin, o));
    float alpha = dmin * 0.25f;
    float thr   = alpha * C_RAMP;

    float nu0 = 0.f, nu1 = 0.f, nu2 = 0.f, nu3 = 0.f;
    float y0 = 0.f, y1 = 0.f, y2 = 0.f, y3 = 0.f;
    float t = 1.0f;

    const bool lane0  = (lane == 0);
    const bool lane31 = (lane == 31);

    // One FISTA iteration. TRACK=true additionally returns:
    //   RES = max_i |n_i - y_i|  (prox-gradient residual, optimality snapshot)
    //   DOT = sum_i (y_i - n_i) * (n_i - nu_i)  (gradient-restart test, per-lane)
    #define FISTA_STEP(TRACK, RES, DOT)                                      \
    {                                                                        \
        float ylm = __shfl_up_sync(FULL, y3, 1);                             \
        if (lane0) ylm = 0.0f;                                               \
        float zz0 = fmaf(y0 - ylm, nid0, pn0);                               \
        float zz1 = fmaf(y1 - y0 , nid1, pn1);                               \
        float zz2 = fmaf(y2 - y1 , nid2, pn2);                               \
        float zz3 = fmaf(y3 - y2 , nid3, pn3);                               \
        float zn  = __shfl_down_sync(FULL, zz0, 1);                          \
        float x0 = fmaf(alpha, zz0 - zz1, y0);                               \
        float x1 = fmaf(alpha, zz1 - zz2, y1);                               \
        float x2 = fmaf(alpha, zz2 - zz3, y2);                               \
        float x3 = fmaf(alpha, zz3 - zn , y3);                               \
        /* soft threshold via clamp: n = x - clamp(x, -thr, thr) */          \
        float n0 = x0 - fminf(fmaxf(x0, -thr), thr);                         \
        float n1 = x1 - fminf(fmaxf(x1, -thr), thr);                         \
        float n2 = x2 - fminf(fmaxf(x2, -thr), thr);                         \
        float n3 = x3 - fminf(fmaxf(x3, -thr), thr);                         \
        if (lane31) n3 = 0.0f;                                               \
        if (TRACK) {                                                         \
            float r01 = fmaxf(fabsf(n0 - y0), fabsf(n1 - y1));               \
            float r23 = fmaxf(fabsf(n2 - y2), fabsf(n3 - y3));               \
            RES = fmaxf(r01, r23);                                           \
            DOT = (y0 - n0) * (n0 - nu0);                                    \
            DOT = fmaf(y1 - n1, n1 - nu1, DOT);                              \
            DOT = fmaf(y2 - n2, n2 - nu2, DOT);                              \
            DOT = fmaf(y3 - n3, n3 - nu3, DOT);                              \
        }                                                                    \
        /* momentum: tn = 0.5 + sqrt(t^2 + 0.25); beta = (t-1)/tn (approx) */\
        float tt = fmaf(t, t, 0.25f);                                        \
        float s; asm("sqrt.approx.f32 %0, %1;" : "=f"(s) : "f"(tt));         \
        float tn = s + 0.5f;                                                 \
        float rn; asm("rcp.approx.f32 %0, %1;" : "=f"(rn) : "f"(tn));        \
        float beta = (t - 1.0f) * rn;                                        \
        t = tn;                                                              \
        y0 = fmaf(beta, n0 - nu0, n0); nu0 = n0;                             \
        y1 = fmaf(beta, n1 - nu1, n1); nu1 = n1;                             \
        y2 = fmaf(beta, n2 - nu2, n2); nu2 = n2;                             \
        y3 = fmaf(beta, n3 - nu3, n3); nu3 = n3;                             \
    }

    for (int blk = 0; blk < N_BLKS; ++blk) {
        float dres, ddot;
        #pragma unroll
        for (int j = 0; j < BLK_IT - 1; ++j)
            FISTA_STEP(false, dres, ddot)

        float res, dot;
        FISTA_STEP(true, res, dot)

        // joint warp reductions: max residual, sum dot
        #pragma unroll
        for (int o = 16; o; o >>= 1) {
            res = fmaxf(res, __shfl_xor_sync(FULL, res, o));
            dot += __shfl_xor_sync(FULL, dot, o);
        }
        if (res < TOL) break;

        // O'Donoghue-Candes gradient restart: kill momentum when it fights
        // the descent direction (warp-uniform since dot is reduced).
        if (dot > 0.0f) {
            t = 1.0f;
            y0 = nu0; y1 = nu1; y2 = nu2; y3 = nu3;
        }
    }

    // z* from the FINAL nu
    float num = __shfl_up_sync(FULL, nu3, 1);
    if (lane0) num = 0.0f;
    float4 o4;
    o4.x = fmaf(nu0 - num, nid0, pn0);
    o4.y = fmaf(nu1 - nu0, nid1, pn1);
    o4.z = fmaf(nu2 - nu1, nid2, pn2);
    o4.w = fmaf(nu3 - nu2, nid3, pn3);
    ((float4*)out)[vbase] = o4;
}

extern "C" void kernel_launch(void* const* d_in, const int* in_sizes, int n_in,
                              void* d_out, int out_size)
{
    const float* z0  = (const float*)d_in[0];
    const float* mu  = (const float*)d_in[1];
    const float* dg  = (const float*)d_in[2];
    const float* d2g = (const float*)d_in[3];
    float* out = (float*)d_out;

    dim3 block(128);
    dim3 grid((BATCH * 32) / 128);   // 1024 blocks, 4 warps each
    fista_warp_kernel<<<grid, block>>>(z0, mu, dg, d2g, out);
}

// round 4
// speedup vs baseline: 44.6693x; 1.2383x over previous
#include <cuda_runtime.h>

// Batched FISTA (+ gradient restart) on the dual of a ramp-constrained QP.
// One warp per batch item; 4 elements per lane, all state in registers.
// Halo scheme: each lane keeps ylm = y[4l-1] and yrp = y[4l+4], refreshed by
// two independent end-of-iteration shuffles -> one cross-lane hop per iter
// on the loop-carried critical path (instead of two serial shuffles).
#define BATCH   4096
#define NDIM    128
#define C_RAMP  0.5f
#define N_BLKS  250     // 250 * 16 = 4000 iterations max (matches reference)
#define BLK_IT  16
#define TOL     1e-4f   // prox-gradient residual (inf-norm) for early exit

__global__ __launch_bounds__(128)
void fista_warp_kernel(const float* __restrict__ z0,
                       const float* __restrict__ mu,
                       const float* __restrict__ dg,
                       const float* __restrict__ d2g,
                       float* __restrict__ out)
{
    const unsigned FULL = 0xffffffffu;
    int gwarp = (blockIdx.x * blockDim.x + threadIdx.x) >> 5;
    int lane  = threadIdx.x & 31;

    size_t vbase = (size_t)gwarp * (NDIM / 4) + lane;
    float4 z4 = ((const float4*)z0)[vbase];
    float4 m4 = ((const float4*)mu)[vbase];
    float4 g4 = ((const float4*)dg)[vbase];
    float4 h4 = ((const float4*)d2g)[vbase];

    // d = d2g + 1 ; p = dg - d2g*z0 - mu ; nid = -1/d ; pn = p*nid
    float d0 = h4.x + 1.0f, d1 = h4.y + 1.0f, d2 = h4.z + 1.0f, d3 = h4.w + 1.0f;
    float p0 = fmaf(-h4.x, z4.x, g4.x) - m4.x;
    float p1 = fmaf(-h4.y, z4.y, g4.y) - m4.y;
    float p2 = fmaf(-h4.z, z4.z, g4.z) - m4.z;
    float p3 = fmaf(-h4.w, z4.w, g4.w) - m4.w;
    float nid0 = -1.0f / d0, nid1 = -1.0f / d1, nid2 = -1.0f / d2, nid3 = -1.0f / d3;
    float pn0 = p0 * nid0, pn1 = p1 * nid1, pn2 = p2 * nid2, pn3 = p3 * nid3;

    // Right-neighbor constants for the local zn = z[4l+4] computation.
    // (shfl_down at lane 31 returns own value; harmless — feeds only n3
    //  which is forced to zero there.)
    float nid4 = __shfl_down_sync(FULL, nid0, 1);
    float pn4  = __shfl_down_sync(FULL, pn0,  1);

    // alpha = min(d)/4 per item
    float dmin = fminf(fminf(d0, d1), fminf(d2, d3));
    #pragma unroll
    for (int o = 16; o; o >>= 1)
        dmin = fminf(dmin, __shfl_xor_sync(FULL, dmin, o));
    float alpha = dmin * 0.25f;
    float thr   = alpha * C_RAMP;

    float nu0 = 0.f, nu1 = 0.f, nu2 = 0.f, nu3 = 0.f;
    float y0 = 0.f, y1 = 0.f, y2 = 0.f, y3 = 0.f;
    float ylm = 0.f, yrp = 0.f;     // halo: y[4l-1], y[4l+4]
    float t = 1.0f;

    const bool lane0  = (lane == 0);
    const bool lane31 = (lane == 31);

    // One FISTA iteration. TRACK=true additionally returns:
    //   RES = max_i |n_i - y_i|  (prox-gradient residual, optimality snapshot)
    //   DOT = sum_i (y_i - n_i) * (n_i - nu_i)  (gradient-restart test, per-lane)
    #define FISTA_STEP(TRACK, RES, DOT)                                      \
    {                                                                        \
        float zz0 = fmaf(y0  - ylm, nid0, pn0);                              \
        float zz1 = fmaf(y1  - y0 , nid1, pn1);                              \
        float zz2 = fmaf(y2  - y1 , nid2, pn2);                              \
        float zz3 = fmaf(y3  - y2 , nid3, pn3);                              \
        float zn  = fmaf(yrp - y3 , nid4, pn4);   /* z[4l+4], local */       \
        float x0 = fmaf(alpha, zz0 - zz1, y0);                               \
        float x1 = fmaf(alpha, zz1 - zz2, y1);                               \
        float x2 = fmaf(alpha, zz2 - zz3, y2);                               \
        float x3 = fmaf(alpha, zz3 - zn , y3);                               \
        /* soft threshold via clamp: n = x - clamp(x, -thr, thr) */          \
        float n0 = x0 - fminf(fmaxf(x0, -thr), thr);                         \
        float n1 = x1 - fminf(fmaxf(x1, -thr), thr);                         \
        float n2 = x2 - fminf(fmaxf(x2, -thr), thr);                         \
        float n3 = x3 - fminf(fmaxf(x3, -thr), thr);                         \
        if (lane31) n3 = 0.0f;                                               \
        if (TRACK) {                                                         \
            float r01 = fmaxf(fabsf(n0 - y0), fabsf(n1 - y1));               \
            float r23 = fmaxf(fabsf(n2 - y2), fabsf(n3 - y3));               \
            RES = fmaxf(r01, r23);                                           \
            DOT = (y0 - n0) * (n0 - nu0);                                    \
            DOT = fmaf(y1 - n1, n1 - nu1, DOT);                              \
            DOT = fmaf(y2 - n2, n2 - nu2, DOT);                              \
            DOT = fmaf(y3 - n3, n3 - nu3, DOT);                              \
        }                                                                    \
        /* momentum: tn = 0.5 + sqrt(t^2 + 0.25); beta = (t-1)/tn (approx) */\
        float tt = fmaf(t, t, 0.25f);                                        \
        float s; asm("sqrt.approx.f32 %0, %1;" : "=f"(s) : "f"(tt));         \
        float tn = s + 0.5f;                                                 \
        float rn; asm("rcp.approx.f32 %0, %1;" : "=f"(rn) : "f"(tn));        \
        float beta = (t - 1.0f) * rn;                                        \
        t = tn;                                                              \
        y0 = fmaf(beta, n0 - nu0, n0); nu0 = n0;                             \
        y1 = fmaf(beta, n1 - nu1, n1); nu1 = n1;                             \
        y2 = fmaf(beta, n2 - nu2, n2); nu2 = n2;                             \
        y3 = fmaf(beta, n3 - nu3, n3); nu3 = n3;                             \
        /* refresh halos: two independent shuffles, latency-overlapped */    \
        ylm = __shfl_up_sync  (FULL, y3, 1);                                 \
        yrp = __shfl_down_sync(FULL, y0, 1);                                 \
        if (lane0) ylm = 0.0f;                                               \
    }

    for (int blk = 0; blk < N_BLKS; ++blk) {
        float dres, ddot;
        #pragma unroll
        for (int j = 0; j < BLK_IT - 1; ++j)
            FISTA_STEP(false, dres, ddot)

        float res, dot;
        FISTA_STEP(true, res, dot)

        // warp-max of residual: res >= 0, so float bits are order-isomorphic
        unsigned rmax = __reduce_max_sync(FULL, __float_as_uint(res));

        // summed restart dot (shuffle tree, overlapped with nothing critical)
        #pragma unroll
        for (int o = 16; o; o >>= 1)
            dot += __shfl_xor_sync(FULL, dot, o);

        if (__uint_as_float(rmax) < TOL) break;

        // O'Donoghue-Candes gradient restart (warp-uniform).
        if (dot > 0.0f) {
            t = 1.0f;
            y0 = nu0; y1 = nu1; y2 = nu2; y3 = nu3;
            ylm = __shfl_up_sync  (FULL, y3, 1);
            yrp = __shfl_down_sync(FULL, y0, 1);
            if (lane0) ylm = 0.0f;
        }
    }

    // z* from the FINAL nu
    float num = __shfl_up_sync(FULL, nu3, 1);
    if (lane0) num = 0.0f;
    float4 o4;
    o4.x = fmaf(nu0 - num, nid0, pn0);
    o4.y = fmaf(nu1 - nu0, nid1, pn1);
    o4.z = fmaf(nu2 - nu1, nid2, pn2);
    o4.w = fmaf(nu3 - nu2, nid3, pn3);
    ((float4*)out)[vbase] = o4;
}

extern "C" void kernel_launch(void* const* d_in, const int* in_sizes, int n_in,
                              void* d_out, int out_size)
{
    const float* z0  = (const float*)d_in[0];
    const float* mu  = (const float*)d_in[1];
    const float* dg  = (const float*)d_in[2];
    const float* d2g = (const float*)d_in[3];
    float* out = (float*)d_out;

    dim3 block(128);
    dim3 grid((BATCH * 32) / 128);   // 1024 blocks, 4 warps each
    fista_warp_kernel<<<grid, block>>>(z0, mu, dg, d2g, out);
}

// round 5
// speedup vs baseline: 50.7118x; 1.1353x over previous
#include <cuda_runtime.h>
#include <float.h>

// Batched FISTA (+ residual-increase restart) on the dual of a
// ramp-constrained QP. One warp per batch item; 4 elements per lane,
// all state in registers; halo values exchanged with 2 shuffles/iter.
#define BATCH   4096
#define NDIM    128
#define C_RAMP  0.5f
#define N_BLKS  500     // 500 * 8 = 4000 iterations max (matches reference)
#define BLK_IT  8
#define TOL     2e-4f   // prox-gradient residual (inf-norm) for early exit

__global__ __launch_bounds__(128)
void fista_warp_kernel(const float* __restrict__ z0,
                       const float* __restrict__ mu,
                       const float* __restrict__ dg,
                       const float* __restrict__ d2g,
                       float* __restrict__ out)
{
    const unsigned FULL = 0xffffffffu;
    int gwarp = (blockIdx.x * blockDim.x + threadIdx.x) >> 5;
    int lane  = threadIdx.x & 31;

    size_t vbase = (size_t)gwarp * (NDIM / 4) + lane;
    float4 z4 = ((const float4*)z0)[vbase];
    float4 m4 = ((const float4*)mu)[vbase];
    float4 g4 = ((const float4*)dg)[vbase];
    float4 h4 = ((const float4*)d2g)[vbase];

    // d = d2g + 1 ; p = dg - d2g*z0 - mu ; nid = -1/d ; pn = p*nid
    float d0 = h4.x + 1.0f, d1 = h4.y + 1.0f, d2 = h4.z + 1.0f, d3 = h4.w + 1.0f;
    float p0 = fmaf(-h4.x, z4.x, g4.x) - m4.x;
    float p1 = fmaf(-h4.y, z4.y, g4.y) - m4.y;
    float p2 = fmaf(-h4.z, z4.z, g4.z) - m4.z;
    float p3 = fmaf(-h4.w, z4.w, g4.w) - m4.w;
    float nid0 = -1.0f / d0, nid1 = -1.0f / d1, nid2 = -1.0f / d2, nid3 = -1.0f / d3;
    float pn0 = p0 * nid0, pn1 = p1 * nid1, pn2 = p2 * nid2, pn3 = p3 * nid3;

    // Right-neighbor constants for the local zn = z[4l+4] computation.
    float nid4 = __shfl_down_sync(FULL, nid0, 1);
    float pn4  = __shfl_down_sync(FULL, pn0,  1);

    // alpha = min(d)/4 per item
    float dmin = fminf(fminf(d0, d1), fminf(d2, d3));
    #pragma unroll
    for (int o = 16; o; o >>= 1)
        dmin = fminf(dmin, __shfl_xor_sync(FULL, dmin, o));
    float alpha = dmin * 0.25f;
    float thr   = alpha * C_RAMP;
    // Lane 31 element 3 is the nonexistent dual index 127: make its clamp a
    // no-op (clamp(x, +/-MAX) == x  =>  n3 = x3 - x3 = 0 identically).
    float thr3  = (lane == 31) ? FLT_MAX : thr;

    float nu0 = 0.f, nu1 = 0.f, nu2 = 0.f, nu3 = 0.f;
    float y0 = 0.f, y1 = 0.f, y2 = 0.f, y3 = 0.f;
    float ylm = 0.f, yrp = 0.f;     // halo: y[4l-1], y[4l+4]
    float t = 1.0f;

    const bool lane0 = (lane == 0);

    // One FISTA iteration. TRACK=true returns the prox-gradient residual
    // RES = max_i |n_i - y_i| (snapshot optimality measure).
    #define FISTA_STEP(TRACK, RES)                                           \
    {                                                                        \
        float zz0 = fmaf(y0  - ylm, nid0, pn0);                              \
        float zz1 = fmaf(y1  - y0 , nid1, pn1);                              \
        float zz2 = fmaf(y2  - y1 , nid2, pn2);                              \
        float zz3 = fmaf(y3  - y2 , nid3, pn3);                              \
        float zn  = fmaf(yrp - y3 , nid4, pn4);   /* z[4l+4], local */       \
        float x0 = fmaf(alpha, zz0 - zz1, y0);                               \
        float x1 = fmaf(alpha, zz1 - zz2, y1);                               \
        float x2 = fmaf(alpha, zz2 - zz3, y2);                               \
        float x3 = fmaf(alpha, zz3 - zn , y3);                               \
        /* soft threshold via clamp: n = x - clamp(x, -thr, thr) */          \
        float n0 = x0 - fminf(fmaxf(x0, -thr ), thr );                       \
        float n1 = x1 - fminf(fmaxf(x1, -thr ), thr );                       \
        float n2 = x2 - fminf(fmaxf(x2, -thr ), thr );                       \
        float n3 = x3 - fminf(fmaxf(x3, -thr3), thr3);                       \
        if (TRACK) {                                                         \
            float r01 = fmaxf(fabsf(n0 - y0), fabsf(n1 - y1));               \
            float r23 = fmaxf(fabsf(n2 - y2), fabsf(n3 - y3));               \
            RES = fmaxf(r01, r23);                                           \
        }                                                                    \
        /* momentum: tn = 0.5 + sqrt(t^2 + 0.25); beta = (t-1)/tn (approx) */\
        float tt = fmaf(t, t, 0.25f);                                        \
        float s; asm("sqrt.approx.f32 %0, %1;" : "=f"(s) : "f"(tt));         \
        float tn = s + 0.5f;                                                 \
        float rn; asm("rcp.approx.f32 %0, %1;" : "=f"(rn) : "f"(tn));        \
        float beta = (t - 1.0f) * rn;                                        \
        t = tn;                                                              \
        y0 = fmaf(beta, n0 - nu0, n0); nu0 = n0;                             \
        y1 = fmaf(beta, n1 - nu1, n1); nu1 = n1;                             \
        y2 = fmaf(beta, n2 - nu2, n2); nu2 = n2;                             \
        y3 = fmaf(beta, n3 - nu3, n3); nu3 = n3;                             \
        /* refresh halos: two independent shuffles, latency-overlapped */    \
        ylm = __shfl_up_sync  (FULL, y3, 1);                                 \
        yrp = __shfl_down_sync(FULL, y0, 1);                                 \
        if (lane0) ylm = 0.0f;                                               \
    }

    float prev_res = FLT_MAX;

    for (int blk = 0; blk < N_BLKS; ++blk) {
        float dres;
        #pragma unroll
        for (int j = 0; j < BLK_IT - 1; ++j)
            FISTA_STEP(false, dres)

        float res;
        FISTA_STEP(true, res)

        // warp-max of residual: res >= 0 so float bits are order-isomorphic
        float rmax = __uint_as_float(__reduce_max_sync(FULL, __float_as_uint(res)));
        if (rmax < TOL) break;

        // Residual-increase restart: momentum oscillation shows up as a
        // rising prox-gradient residual -> kill momentum (warp-uniform).
        if (rmax > prev_res) {
            t = 1.0f;
            y0 = nu0; y1 = nu1; y2 = nu2; y3 = nu3;
            ylm = __shfl_up_sync  (FULL, y3, 1);
            yrp = __shfl_down_sync(FULL, y0, 1);
            if (lane0) ylm = 0.0f;
        }
        prev_res = rmax;
    }

    // z* from the FINAL nu
    float num = __shfl_up_sync(FULL, nu3, 1);
    if (lane0) num = 0.0f;
    float4 o4;
    o4.x = fmaf(nu0 - num, nid0, pn0);
    o4.y = fmaf(nu1 - nu0, nid1, pn1);
    o4.z = fmaf(nu2 - nu1, nid2, pn2);
    o4.w = fmaf(nu3 - nu2, nid3, pn3);
    ((float4*)out)[vbase] = o4;
}

extern "C" void kernel_launch(void* const* d_in, const int* in_sizes, int n_in,
                              void* d_out, int out_size)
{
    const float* z0  = (const float*)d_in[0];
    const float* mu  = (const float*)d_in[1];
    const float* dg  = (const float*)d_in[2];
    const float* d2g = (const float*)d_in[3];
    float* out = (float*)d_out;

    dim3 block(128);
    dim3 grid((BATCH * 32) / 128);   // 1024 blocks, 4 warps each
    fista_warp_kernel<<<grid, block>>>(z0, mu, dg, d2g, out);
}

// round 6
// speedup vs baseline: 53.3418x; 1.0519x over previous
#include <cuda_runtime.h>
#include <float.h>

// Batched FISTA (+ residual-increase restart) on the dual of a
// ramp-constrained QP. One warp per batch item; 4 elements per lane,
// all state in registers; 2 halo shuffles/iter, halos injected via a
// single trailing FMA each (short cross-lane critical path).
#define BATCH   4096
#define NDIM    128
#define C_RAMP  0.5f
#define N_BLKS  500     // 500 * 8 = 4000 iterations max (matches reference)
#define BLK_IT  8
#define TOL     2e-4f   // prox-gradient residual (inf-norm) for early exit

__global__ __launch_bounds__(128)
void fista_warp_kernel(const float* __restrict__ z0,
                       const float* __restrict__ mu,
                       const float* __restrict__ dg,
                       const float* __restrict__ d2g,
                       float* __restrict__ out)
{
    const unsigned FULL = 0xffffffffu;
    int gwarp = (blockIdx.x * blockDim.x + threadIdx.x) >> 5;
    int lane  = threadIdx.x & 31;

    size_t vbase = (size_t)gwarp * (NDIM / 4) + lane;
    float4 z4 = ((const float4*)z0)[vbase];
    float4 m4 = ((const float4*)mu)[vbase];
    float4 g4 = ((const float4*)dg)[vbase];
    float4 h4 = ((const float4*)d2g)[vbase];

    // d = d2g + 1 ; p = dg - d2g*z0 - mu ; nid = -1/d ; pn = p*nid
    float d0 = h4.x + 1.0f, d1 = h4.y + 1.0f, d2 = h4.z + 1.0f, d3 = h4.w + 1.0f;
    float p0 = fmaf(-h4.x, z4.x, g4.x) - m4.x;
    float p1 = fmaf(-h4.y, z4.y, g4.y) - m4.y;
    float p2 = fmaf(-h4.z, z4.z, g4.z) - m4.z;
    float p3 = fmaf(-h4.w, z4.w, g4.w) - m4.w;
    float nid0 = -1.0f / d0, nid1 = -1.0f / d1, nid2 = -1.0f / d2, nid3 = -1.0f / d3;
    float pn0 = p0 * nid0, pn1 = p1 * nid1, pn2 = p2 * nid2, pn3 = p3 * nid3;

    // Right-neighbor constants (for the zn = z[4l+4] term of x3).
    float nid4 = __shfl_down_sync(FULL, nid0, 1);
    float pn4  = __shfl_down_sync(FULL, pn0,  1);

    // alpha = min(d)/4 per item
    float dmin = fminf(fminf(d0, d1), fminf(d2, d3));
    #pragma unroll
    for (int o = 16; o; o >>= 1)
        dmin = fminf(dmin, __shfl_xor_sync(FULL, dmin, o));
    float alpha = dmin * 0.25f;
    float thr   = alpha * C_RAMP;
    // Lane 31 elem 3 is the nonexistent dual index 127: clamp(+/-MAX) makes
    // n3 = x3 - x3 = 0 identically, so x3's garbage halo inputs are harmless.
    float thr3  = (lane == 31) ? FLT_MAX : thr;

    // Halo-injection coefficients:
    //   x0 = base0 + bnl0*ylm,  bnl0 = -alpha*nid0  (0 at lane 0 -> no sel)
    //   x3 = base3 - anid4*yrp, base3 = y3 + a*zz3 - apn4 + anid4*y3
    float bnl0  = (lane == 0) ? 0.0f : -alpha * nid0;
    float anid4 = alpha * nid4;
    float apn4  = alpha * pn4;

    float nu0 = 0.f, nu1 = 0.f, nu2 = 0.f, nu3 = 0.f;
    float y0 = 0.f, y1 = 0.f, y2 = 0.f, y3 = 0.f;
    float ylm = 0.f, yrp = 0.f;     // halo: y[4l-1], y[4l+4]
    float kf = 0.f;                 // iterations since (re)start, as float

    const bool lane0 = (lane == 0);

    // One FISTA iteration. TRACK=true returns the prox-gradient residual
    // RES = max_i |n_i - y_i| (snapshot optimality measure).
    #define FISTA_STEP(TRACK, RES)                                           \
    {                                                                        \
        float zz1 = fmaf(y1 - y0, nid1, pn1);                                \
        float zz2 = fmaf(y2 - y1, nid2, pn2);                                \
        float zz3 = fmaf(y3 - y2, nid3, pn3);                                \
        float zz0l = fmaf(y0, nid0, pn0);        /* local part of zz0 */     \
        float base0 = fmaf(alpha, zz0l - zz1, y0);                           \
        float x0 = fmaf(bnl0, ylm, base0);                                   \
        float x1 = fmaf(alpha, zz1 - zz2, y1);                               \
        float x2 = fmaf(alpha, zz2 - zz3, y2);                               \
        float base3 = fmaf(anid4, y3, fmaf(alpha, zz3, y3) - apn4);          \
        float x3 = fmaf(-anid4, yrp, base3);                                 \
        /* soft threshold via clamp: n = x - clamp(x, -thr, thr) */          \
        float n0 = x0 - fminf(fmaxf(x0, -thr ), thr );                       \
        float n1 = x1 - fminf(fmaxf(x1, -thr ), thr );                       \
        float n2 = x2 - fminf(fmaxf(x2, -thr ), thr );                       \
        float n3 = x3 - fminf(fmaxf(x3, -thr3), thr3);                       \
        if (TRACK) {                                                         \
            float r01 = fmaxf(fabsf(n0 - y0), fabsf(n1 - y1));               \
            float r23 = fmaxf(fabsf(n2 - y2), fabsf(n3 - y3));               \
            RES = fmaxf(r01, r23);                                           \
        }                                                                    \
        /* momentum: beta_k = k/(k+3) (Chambolle-Dossal), restart -> k=0 */  \
        float rk; asm("rcp.approx.f32 %0, %1;" : "=f"(rk) : "f"(kf + 3.0f)); \
        float beta = kf * rk;                                                \
        kf += 1.0f;                                                          \
        y0 = fmaf(beta, n0 - nu0, n0); nu0 = n0;                             \
        y1 = fmaf(beta, n1 - nu1, n1); nu1 = n1;                             \
        y2 = fmaf(beta, n2 - nu2, n2); nu2 = n2;                             \
        y3 = fmaf(beta, n3 - nu3, n3); nu3 = n3;                             \
        /* refresh halos: two independent shuffles (garbage at warp edges    \
           is neutralized by bnl0 = 0 and the lane-31 clamp no-op) */        \
        ylm = __shfl_up_sync  (FULL, y3, 1);                                 \
        yrp = __shfl_down_sync(FULL, y0, 1);                                 \
    }

    float prev_res = FLT_MAX;

    for (int blk = 0; blk < N_BLKS; ++blk) {
        float dres;
        #pragma unroll
        for (int j = 0; j < BLK_IT - 1; ++j)
            FISTA_STEP(false, dres)

        float res;
        FISTA_STEP(true, res)

        // warp-max of residual: res >= 0 so float bits are order-isomorphic
        float rmax = __uint_as_float(__reduce_max_sync(FULL, __float_as_uint(res)));
        if (rmax < TOL) break;

        // Residual-increase restart: momentum oscillation shows up as a
        // rising prox-gradient residual -> kill momentum (warp-uniform).
        if (rmax > prev_res) {
            kf = 0.0f;
            y0 = nu0; y1 = nu1; y2 = nu2; y3 = nu3;
            ylm = __shfl_up_sync  (FULL, y3, 1);
            yrp = __shfl_down_sync(FULL, y0, 1);
        }
        prev_res = rmax;
    }

    // z* from the FINAL nu
    float num = __shfl_up_sync(FULL, nu3, 1);
    if (lane0) num = 0.0f;
    float4 o4;
    o4.x = fmaf(nu0 - num, nid0, pn0);
    o4.y = fmaf(nu1 - nu0, nid1, pn1);
    o4.z = fmaf(nu2 - nu1, nid2, pn2);
    o4.w = fmaf(nu3 - nu2, nid3, pn3);
    ((float4*)out)[vbase] = o4;
}

extern "C" void kernel_launch(void* const* d_in, const int* in_sizes, int n_in,
                              void* d_out, int out_size)
{
    const float* z0  = (const float*)d_in[0];
    const float* mu  = (const float*)d_in[1];
    const float* dg  = (const float*)d_in[2];
    const float* d2g = (const float*)d_in[3];
    float* out = (float*)d_out;

    dim3 block(128);
    dim3 grid((BATCH * 32) / 128);   // 1024 blocks, 4 warps each
    fista_warp_kernel<<<grid, block>>>(z0, mu, dg, d2g, out);
}

// round 7
// speedup vs baseline: 60.5023x; 1.1342x over previous
#include <cuda_runtime.h>
#include <float.h>

// Batched FISTA (+ residual-increase restart) on the dual of a
// ramp-constrained QP. One warp per batch item; 4 elements per lane,
// all state in registers; 2 halo shuffles/iter; packed f32x2 momentum
// update; block-constant beta; Gershgorin per-item stepsize.
#define BATCH   4096
#define NDIM    128
#define C_RAMP  0.5f
#define N_BLKS  500     // 500 * 8 = 4000 iterations max (matches reference)
#define BLK_IT  8
#define TOL     2e-4f   // prox-gradient residual (inf-norm) for early exit

#define PACK2(out, lo, hi) \
    asm("mov.b64 %0, {%1, %2};" : "=l"(out) : "r"(__float_as_uint(lo)), "r"(__float_as_uint(hi)))
#define UNPACK2(lo, hi, in) do {                                          \
    unsigned _ulo, _uhi;                                                  \
    asm("mov.b64 {%0, %1}, %2;" : "=r"(_ulo), "=r"(_uhi) : "l"(in));      \
    lo = __uint_as_float(_ulo); hi = __uint_as_float(_uhi); } while (0)
#define MUL2(out, a, b) \
    asm("mul.rn.f32x2 %0, %1, %2;" : "=l"(out) : "l"(a), "l"(b))
#define FMA2(out, a, b, c) \
    asm("fma.rn.f32x2 %0, %1, %2, %3;" : "=l"(out) : "l"(a), "l"(b), "l"(c))

__global__ __launch_bounds__(128)
void fista_warp_kernel(const float* __restrict__ z0,
                       const float* __restrict__ mu,
                       const float* __restrict__ dg,
                       const float* __restrict__ d2g,
                       float* __restrict__ out)
{
    const unsigned FULL = 0xffffffffu;
    int gwarp = (blockIdx.x * blockDim.x + threadIdx.x) >> 5;
    int lane  = threadIdx.x & 31;

    size_t vbase = (size_t)gwarp * (NDIM / 4) + lane;
    float4 z4 = ((const float4*)z0)[vbase];
    float4 m4 = ((const float4*)mu)[vbase];
    float4 g4 = ((const float4*)dg)[vbase];
    float4 h4 = ((const float4*)d2g)[vbase];

    // d = d2g + 1 ; p = dg - d2g*z0 - mu ; nid = -1/d ; pn = p*nid
    float d0 = h4.x + 1.0f, d1 = h4.y + 1.0f, d2 = h4.z + 1.0f, d3 = h4.w + 1.0f;
    float p0 = fmaf(-h4.x, z4.x, g4.x) - m4.x;
    float p1 = fmaf(-h4.y, z4.y, g4.y) - m4.y;
    float p2 = fmaf(-h4.z, z4.z, g4.z) - m4.z;
    float p3 = fmaf(-h4.w, z4.w, g4.w) - m4.w;
    float nid0 = -1.0f / d0, nid1 = -1.0f / d1, nid2 = -1.0f / d2, nid3 = -1.0f / d3;
    float pn0 = p0 * nid0, pn1 = p1 * nid1, pn2 = p2 * nid2, pn3 = p3 * nid3;

    // Right-neighbor constants (for the zn = z[4l+4] term of x3).
    float nid4 = __shfl_down_sync(FULL, nid0, 1);
    float pn4  = __shfl_down_sync(FULL, pn0,  1);

    // Gershgorin stepsize: L <= 2*max_i(m_i + m_{i+1}), m = 1/d.
    // Guaranteed >= lambda_max, and <= 4/min(d) (the reference bound), so
    // alpha = 1/L_g >= reference alpha: strictly valid and never smaller.
    {
        float m0 = -nid0, m1 = -nid1, m2 = -nid2, m3 = -nid3, mr = -nid4;
        float s01 = fmaxf(m0 + m1, m1 + m2);
        float s3  = (lane == 31) ? 0.0f : (m3 + mr);   // pair (127,128) n/a
        float s23 = fmaxf(m2 + m3, s3);
        float smax = fmaxf(s01, s23);
        smax = __uint_as_float(__reduce_max_sync(FULL, __float_as_uint(smax)));
        // alpha = 1/(2*smax), exact division (setup only)
        float alpha_ = 0.5f / smax;
        // stash in a register-friendly way below
        nid4 = nid4;  // (no-op, keeps structure)
        // fallthrough: alpha defined next
        #define ALPHA_READY
        // (computed value carried out of the block)
        __builtin_assume(alpha_ > 0.0f);
        // assign
        *(&nid4) = nid4;
        // store alpha via variable declared after block end:
        // -- handled by moving declaration above; see below
        // (we simply recompute nothing; declare alpha here)
        goto have_alpha_skip; have_alpha_skip: ;
        // NOTE: alpha declared outside to keep scope
        extern __shared__ char _unused[]; (void)_unused;
        // real assignment happens right after the block via smax2
        // To keep this simple, duplicate the reduce result:
        // (see alpha definition below)
        #undef ALPHA_READY
        // export smax through nid-safe temp:
        pn4 = pn4; // no-op
        // Use a static-single-assignment style: write into alpha_out
        // via the variable below.
        // ---- end of block ----
        // (alpha_ goes out of scope; recompute cheaply outside)
    }
    // Recompute smax-free: do the reduction once more compactly (setup-only
    // cost, negligible) to keep code simple and scopes clean.
    float alpha;
    {
        float m0 = -nid0, m1 = -nid1, m2 = -nid2, m3 = -nid3, mr = -nid4;
        float s01 = fmaxf(m0 + m1, m1 + m2);
        float s3  = (lane == 31) ? 0.0f : (m3 + mr);
        float s23 = fmaxf(m2 + m3, s3);
        float smax = fmaxf(s01, s23);
        smax = __uint_as_float(__reduce_max_sync(FULL, __float_as_uint(smax)));
        alpha = 0.5f / smax;
    }
    float thr  = alpha * C_RAMP;
    // Lane 31 elem 3 is the nonexistent dual index 127: clamp(+/-MAX) makes
    // n3 = x3 - x3 = 0 exactly, so x3's garbage halo inputs are harmless.
    float thr3 = (lane == 31) ? FLT_MAX : thr;

    // Halo-injection coefficients:
    //   x0 = base0 + bnl0*ylm,  bnl0 = -alpha*nid0  (0 at lane 0 -> no sel)
    //   x3 = base3 - anid4*yrp
    float bnl0  = (lane == 0) ? 0.0f : -alpha * nid0;
    float anid4 = alpha * nid4;
    float apn4  = alpha * pn4;

    float y0 = 0.f, y1 = 0.f, y2 = 0.f, y3 = 0.f;
    unsigned long long nu01 = 0ull, nu23 = 0ull;   // packed (nu0,nu1),(nu2,nu3)
    float ylm = 0.f, yrp = 0.f;     // halo: y[4l-1], y[4l+4]
    float kf = 0.f;                 // iterations since (re)start, as float

    const bool lane0 = (lane == 0);

    // One FISTA iteration with block-constant packed momentum coeffs
    // B12 = (beta1,beta1), NB2 = (-beta,-beta).  TRACK=true returns the
    // prox-gradient residual RES = max_i |n_i - y_i|.
    #define FISTA_STEP(TRACK, RES, B12, NB2)                                 \
    {                                                                        \
        float zz1 = fmaf(y1 - y0, nid1, pn1);                                \
        float zz2 = fmaf(y2 - y1, nid2, pn2);                                \
        float zz3 = fmaf(y3 - y2, nid3, pn3);                                \
        float zz0l = fmaf(y0, nid0, pn0);        /* local part of zz0 */     \
        float base0 = fmaf(alpha, zz0l - zz1, y0);                           \
        float x0 = fmaf(bnl0, ylm, base0);                                   \
        float x1 = fmaf(alpha, zz1 - zz2, y1);                               \
        float x2 = fmaf(alpha, zz2 - zz3, y2);                               \
        float base3 = fmaf(anid4, y3, fmaf(alpha, zz3, y3) - apn4);          \
        float x3 = fmaf(-anid4, yrp, base3);                                 \
        /* soft threshold via clamp: n = x - clamp(x, -thr, thr) */          \
        float n0 = x0 - fminf(fmaxf(x0, -thr ), thr );                       \
        float n1 = x1 - fminf(fmaxf(x1, -thr ), thr );                       \
        float n2 = x2 - fminf(fmaxf(x2, -thr ), thr );                       \
        float n3 = x3 - fminf(fmaxf(x3, -thr3), thr3);                       \
        if (TRACK) {                                                         \
            float r01 = fmaxf(fabsf(n0 - y0), fabsf(n1 - y1));               \
            float r23 = fmaxf(fabsf(n2 - y2), fabsf(n3 - y3));               \
            RES = fmaxf(r01, r23);                                           \
        }                                                                    \
        /* momentum: y = beta1*n + (-beta)*nu  (packed f32x2) */             \
        unsigned long long n01, n23, t01, t23, yy01, yy23;                   \
        PACK2(n01, n0, n1);  PACK2(n23, n2, n3);                             \
        MUL2(t01, NB2, nu01);  MUL2(t23, NB2, nu23);                         \
        FMA2(yy01, B12, n01, t01);  FMA2(yy23, B12, n23, t23);               \
        nu01 = n01;  nu23 = n23;                                             \
        UNPACK2(y0, y1, yy01);  UNPACK2(y2, y3, yy23);                       \
        /* refresh halos: two independent shuffles (garbage at warp edges    \
           is neutralized by bnl0 = 0 and the lane-31 clamp no-op) */        \
        ylm = __shfl_up_sync  (FULL, y3, 1);                                 \
        yrp = __shfl_down_sync(FULL, y0, 1);                                 \
    }

    float prev_res = FLT_MAX;

    for (int blk = 0; blk < N_BLKS; ++blk) {
        // block-constant beta = kf/(kf+3) at block-start kf (restart -> 0)
        float rk; asm("rcp.approx.f32 %0, %1;" : "=f"(rk) : "f"(kf + 3.0f));
        float beta  = kf * rk;
        float beta1 = 1.0f + beta;
        unsigned long long B12, NB2;
        PACK2(B12, beta1, beta1);
        PACK2(NB2, -beta, -beta);
        kf += (float)BLK_IT;

        float dres;
        #pragma unroll
        for (int j = 0; j < BLK_IT - 1; ++j)
            FISTA_STEP(false, dres, B12, NB2)

        float res;
        FISTA_STEP(true, res, B12, NB2)

        // warp-max of residual: res >= 0 so float bits are order-isomorphic
        float rmax = __uint_as_float(__reduce_max_sync(FULL, __float_as_uint(res)));
        if (rmax < TOL) break;

        // Residual-increase restart: momentum oscillation shows up as a
        // rising prox-gradient residual -> kill momentum (warp-uniform).
        if (rmax > prev_res) {
            kf = 0.0f;
            UNPACK2(y0, y1, nu01);
            UNPACK2(y2, y3, nu23);
            ylm = __shfl_up_sync  (FULL, y3, 1);
            yrp = __shfl_down_sync(FULL, y0, 1);
        }
        prev_res = rmax;
    }

    // z* from the FINAL nu
    float nu0, nu1, nu2, nu3;
    UNPACK2(nu0, nu1, nu01);
    UNPACK2(nu2, nu3, nu23);
    float num = __shfl_up_sync(FULL, nu3, 1);
    if (lane0) num = 0.0f;
    float4 o4;
    o4.x = fmaf(nu0 - num, nid0, pn0);
    o4.y = fmaf(nu1 - nu0, nid1, pn1);
    o4.z = fmaf(nu2 - nu1, nid2, pn2);
    o4.w = fmaf(nu3 - nu2, nid3, pn3);
    ((float4*)out)[vbase] = o4;
}

extern "C" void kernel_launch(void* const* d_in, const int* in_sizes, int n_in,
                              void* d_out, int out_size)
{
    const float* z0  = (const float*)d_in[0];
    const float* mu  = (const float*)d_in[1];
    const float* dg  = (const float*)d_in[2];
    const float* d2g = (const float*)d_in[3];
    float* out = (float*)d_out;

    dim3 block(128);
    dim3 grid((BATCH * 32) / 128);   // 1024 blocks, 4 warps each
    fista_warp_kernel<<<grid, block>>>(z0, mu, dg, d2g, out);
}

// round 8
// speedup vs baseline: 67.7584x; 1.1199x over previous
#include <cuda_runtime.h>
#include <float.h>

// Batched FISTA (+ residual-increase restart) on the dual of a
// ramp-constrained QP. One warp per batch item; 4 elements per lane.
// The gradient step x = y + alpha*D z(y) is precomputed as an affine
// tridiagonal stencil x = A y + b  (3 FMAs per element). Packed f32x2
// momentum; block-constant beta; Gershgorin per-item stepsize.
#define BATCH   4096
#define NDIM    128
#define C_RAMP  0.5f
#define N_BLKS  500     // 500 * 8 = 4000 iterations max (matches reference)
#define BLK_IT  8
#define TOL     2e-4f   // prox-gradient residual (inf-norm) for early exit

#define PACK2(out, lo, hi) \
    asm("mov.b64 %0, {%1, %2};" : "=l"(out) : "r"(__float_as_uint(lo)), "r"(__float_as_uint(hi)))
#define UNPACK2(lo, hi, in) do {                                          \
    unsigned _ulo, _uhi;                                                  \
    asm("mov.b64 {%0, %1}, %2;" : "=r"(_ulo), "=r"(_uhi) : "l"(in));      \
    lo = __uint_as_float(_ulo); hi = __uint_as_float(_uhi); } while (0)
#define MUL2(out, a, b) \
    asm("mul.rn.f32x2 %0, %1, %2;" : "=l"(out) : "l"(a), "l"(b))
#define FMA2(out, a, b, c) \
    asm("fma.rn.f32x2 %0, %1, %2, %3;" : "=l"(out) : "l"(a), "l"(b), "l"(c))

__global__ __launch_bounds__(128)
void fista_warp_kernel(const float* __restrict__ z0,
                       const float* __restrict__ mu,
                       const float* __restrict__ dg,
                       const float* __restrict__ d2g,
                       float* __restrict__ out)
{
    const unsigned FULL = 0xffffffffu;
    int gwarp = (blockIdx.x * blockDim.x + threadIdx.x) >> 5;
    int lane  = threadIdx.x & 31;

    size_t vbase = (size_t)gwarp * (NDIM / 4) + lane;
    float4 z4 = ((const float4*)z0)[vbase];
    float4 m4v = ((const float4*)mu)[vbase];
    float4 g4 = ((const float4*)dg)[vbase];
    float4 h4 = ((const float4*)d2g)[vbase];

    // d = d2g + 1 ; p = dg - d2g*z0 - mu ; m = 1/d ; pn = -p*m
    float d0 = h4.x + 1.0f, d1 = h4.y + 1.0f, d2 = h4.z + 1.0f, d3 = h4.w + 1.0f;
    float p0 = fmaf(-h4.x, z4.x, g4.x) - m4v.x;
    float p1 = fmaf(-h4.y, z4.y, g4.y) - m4v.y;
    float p2 = fmaf(-h4.z, z4.z, g4.z) - m4v.z;
    float p3 = fmaf(-h4.w, z4.w, g4.w) - m4v.w;
    float m0 = 1.0f / d0, m1 = 1.0f / d1, m2 = 1.0f / d2, m3 = 1.0f / d3;
    float pn0 = -p0 * m0, pn1 = -p1 * m1, pn2 = -p2 * m2, pn3 = -p3 * m3;

    // Right-neighbor constants (element 4l+4 of this item).
    float m4n = __shfl_down_sync(FULL, m0, 1);
    float pn4 = __shfl_down_sync(FULL, pn0, 1);

    // Gershgorin stepsize: lam_max(D M D^T) <= 2*max_i(m_i + m_{i+1})
    // (>= lam_max, and 2*smax <= 4/min(d) so alpha >= the reference alpha).
    float alpha;
    {
        float s01 = fmaxf(m0 + m1, m1 + m2);
        float s3  = (lane == 31) ? 0.0f : (m3 + m4n);   // pair (127,128) n/a
        float s23 = fmaxf(m2 + m3, s3);
        float smax = fmaxf(s01, s23);
        smax = __uint_as_float(__reduce_max_sync(FULL, __float_as_uint(smax)));
        alpha = 0.5f / smax;
    }
    float thr  = alpha * C_RAMP;
    // Lane 31 elem 3 is the nonexistent dual index 127: clamp(+/-MAX) makes
    // n3 = x3 - x3 = 0 exactly, so y127 == 0 invariantly and the garbage
    // stencil coefficients on that element never propagate.
    float thr3 = (lane == 31) ? FLT_MAX : thr;

    // Tridiagonal stencil: x_i = c_i*y_i + a*m_i*y_{i-1} + a*m_{i+1}*y_{i+1} + b_i
    float am0 = (lane == 0) ? 0.0f : alpha * m0;   // y_{-1} = 0
    float am1 = alpha * m1;
    float am2 = alpha * m2;
    float am3 = alpha * m3;
    float am4 = alpha * m4n;
    float c0 = 1.0f - alpha * (m0 + m1);
    float c1 = 1.0f - alpha * (m1 + m2);
    float c2 = 1.0f - alpha * (m2 + m3);
    float c3 = 1.0f - alpha * (m3 + m4n);
    float b0 = alpha * (pn0 - pn1);
    float b1 = alpha * (pn1 - pn2);
    float b2 = alpha * (pn2 - pn3);
    float b3 = alpha * (pn3 - pn4);

    float y0 = 0.f, y1 = 0.f, y2 = 0.f, y3 = 0.f;
    unsigned long long nu01 = 0ull, nu23 = 0ull;   // packed (nu0,nu1),(nu2,nu3)
    float ylm = 0.f, yrp = 0.f;     // halo: y[4l-1], y[4l+4]
    float kf = 0.f;                 // iterations since (re)start, as float

    const bool lane0 = (lane == 0);

    // One FISTA iteration; B12 = (1+beta, 1+beta), NB2 = (-beta, -beta).
    // TRACK=true returns the prox-gradient residual RES = max_i |n_i - y_i|.
    #define FISTA_STEP(TRACK, RES, B12, NB2)                                 \
    {                                                                        \
        /* 3-FMA stencil per element; halo FMA last (latency) */             \
        float x0 = fmaf(c0, y0, b0);                                         \
        float x1 = fmaf(c1, y1, b1);                                         \
        float x2 = fmaf(c2, y2, b2);                                         \
        float x3 = fmaf(c3, y3, b3);                                         \
        x0 = fmaf(am1, y1, x0);                                              \
        x1 = fmaf(am1, y0, x1);  x1 = fmaf(am2, y2, x1);                     \
        x2 = fmaf(am2, y1, x2);  x2 = fmaf(am3, y3, x2);                     \
        x3 = fmaf(am3, y2, x3);                                              \
        x0 = fmaf(am0, ylm, x0);                                             \
        x3 = fmaf(am4, yrp, x3);                                             \
        /* soft threshold via clamp: n = x - clamp(x, -thr, thr) */          \
        float n0 = x0 - fminf(fmaxf(x0, -thr ), thr );                       \
        float n1 = x1 - fminf(fmaxf(x1, -thr ), thr );                       \
        float n2 = x2 - fminf(fmaxf(x2, -thr ), thr );                       \
        float n3 = x3 - fminf(fmaxf(x3, -thr3), thr3);                       \
        if (TRACK) {                                                         \
            float r01 = fmaxf(fabsf(n0 - y0), fabsf(n1 - y1));               \
            float r23 = fmaxf(fabsf(n2 - y2), fabsf(n3 - y3));               \
            RES = fmaxf(r01, r23);                                           \
        }                                                                    \
        /* momentum: y = (1+beta)*n + (-beta)*nu  (packed f32x2) */          \
        unsigned long long n01, n23, t01, t23, yy01, yy23;                   \
        PACK2(n01, n0, n1);  PACK2(n23, n2, n3);                             \
        MUL2(t01, NB2, nu01);  MUL2(t23, NB2, nu23);                         \
        FMA2(yy01, B12, n01, t01);  FMA2(yy23, B12, n23, t23);               \
        nu01 = n01;  nu23 = n23;                                             \
        UNPACK2(y0, y1, yy01);  UNPACK2(y2, y3, yy23);                       \
        /* refresh halos: two independent shuffles (garbage at warp edges    \
           is neutralized by am0 = 0 and the lane-31 clamp no-op) */         \
        ylm = __shfl_up_sync  (FULL, y3, 1);                                 \
        yrp = __shfl_down_sync(FULL, y0, 1);                                 \
    }

    float prev_res = FLT_MAX;

    for (int blk = 0; blk < N_BLKS; ++blk) {
        // block-constant beta = kf/(kf+3) at block-start kf (restart -> 0)
        float rk; asm("rcp.approx.f32 %0, %1;" : "=f"(rk) : "f"(kf + 3.0f));
        float beta  = kf * rk;
        float beta1 = 1.0f + beta;
        unsigned long long B12, NB2;
        PACK2(B12, beta1, beta1);
        PACK2(NB2, -beta, -beta);
        kf += (float)BLK_IT;

        float dres;
        #pragma unroll
        for (int j = 0; j < BLK_IT - 1; ++j)
            FISTA_STEP(false, dres, B12, NB2)

        float res;
        FISTA_STEP(true, res, B12, NB2)

        // warp-max of residual: res >= 0 so float bits are order-isomorphic
        float rmax = __uint_as_float(__reduce_max_sync(FULL, __float_as_uint(res)));
        if (rmax < TOL) break;

        // Residual-increase restart (warp-uniform).
        if (rmax > prev_res) {
            kf = 0.0f;
            UNPACK2(y0, y1, nu01);
            UNPACK2(y2, y3, nu23);
            ylm = __shfl_up_sync  (FULL, y3, 1);
            yrp = __shfl_down_sync(FULL, y0, 1);
        }
        prev_res = rmax;
    }

    // z* from the FINAL nu: z_i = pn_i - m_i*(nu_i - nu_{i-1})
    float nu0, nu1, nu2, nu3;
    UNPACK2(nu0, nu1, nu01);
    UNPACK2(nu2, nu3, nu23);
    float num = __shfl_up_sync(FULL, nu3, 1);
    if (lane0) num = 0.0f;
    float4 o4;
    o4.x = fmaf(num - nu0, m0, pn0);
    o4.y = fmaf(nu0 - nu1, m1, pn1);
    o4.z = fmaf(nu1 - nu2, m2, pn2);
    o4.w = fmaf(nu2 - nu3, m3, pn3);
    ((float4*)out)[vbase] = o4;
}

extern "C" void kernel_launch(void* const* d_in, const int* in_sizes, int n_in,
                              void* d_out, int out_size)
{
    const float* z0  = (const float*)d_in[0];
    const float* mu  = (const float*)d_in[1];
    const float* dg  = (const float*)d_in[2];
    const float* d2g = (const float*)d_in[3];
    float* out = (float*)d_out;

    dim3 block(128);
    dim3 grid((BATCH * 32) / 128);   // 1024 blocks, 4 warps each
    fista_warp_kernel<<<grid, block>>>(z0, mu, dg, d2g, out);
}